// round 12
// baseline (speedup 1.0000x reference)
#include <cuda_runtime.h>
#include <cuda_bf16.h>
#include <cstdint>

#define BATCH 4
#define NTOK 4096        // H*W
#define CDIM 64
#define DDIM 8
#define QB 128           // queries per CTA
#define LOG2E 1.4426950408889634f

typedef unsigned int u32;

// group barrier: 256 threads, barrier id 1 or 2
#define GBAR(id) asm volatile("bar.sync %0, %1;" :: "r"(id), "r"(256) : "memory")

__device__ __forceinline__ float ex2f(float x) {
    float r;
    asm("ex2.approx.f32 %0, %1;" : "=f"(r) : "f"(x));
    return r;
}
__device__ __forceinline__ u32 pack_bf16(float hi, float lo) {
    u32 r;
    asm("cvt.rn.bf16x2.f32 %0, %1, %2;" : "=r"(r) : "f"(hi), "f"(lo));
    return r;
}

__device__ __forceinline__ void mma_bf16(float* d,
                                         u32 a0, u32 a1, u32 a2, u32 a3,
                                         u32 b0, u32 b1) {
    asm("mma.sync.aligned.m16n8k16.row.col.f32.bf16.bf16.f32 "
        "{%0,%1,%2,%3}, {%4,%5,%6,%7}, {%8,%9}, {%0,%1,%2,%3};"
        : "+f"(d[0]), "+f"(d[1]), "+f"(d[2]), "+f"(d[3])
        : "r"(a0), "r"(a1), "r"(a2), "r"(a3), "r"(b0), "r"(b1));
}
__device__ __forceinline__ void mma_bf16_z(float* d,
                                           u32 a0, u32 a1, u32 a2, u32 a3,
                                           u32 b0, u32 b1) {
    asm("mma.sync.aligned.m16n8k16.row.col.f32.bf16.bf16.f32 "
        "{%0,%1,%2,%3}, {%4,%5,%6,%7}, {%8,%9}, {%10,%11,%12,%13};"
        : "=f"(d[0]), "=f"(d[1]), "=f"(d[2]), "=f"(d[3])
        : "r"(a0), "r"(a1), "r"(a2), "r"(a3), "r"(b0), "r"(b1),
          "f"(0.0f), "f"(0.0f), "f"(0.0f), "f"(0.0f));
}

// ---------------- scratch ----------------
__device__ float g_q[BATCH * NTOK * DDIM];            // fp32 q, pre-scaled by log2(e)
__device__ u32 g_kp[BATCH * NTOK * 8];                // bf16 split k, packed per key
__device__ __nv_bfloat16 g_vb[(size_t)BATCH * CDIM * NTOK];  // bf16 v, ch-major, key-permuted

// position of key j (0..31) within its 32-block in g_vb / Vs
__device__ __forceinline__ int vperm(int j) {
    const int blk = j >> 4;
    const int k   = j & 15;
    const int rho = 4 * ((k >> 1) & 3) + (k & 1) + 2 * (k >> 3);
    return (rho >> 2) * 8 + blk * 4 + (rho & 3);
}

// ---------------------------------------------------------------------------
// Projection. 128 threads, 64 rows/CTA (2 threads per row). Split accumulators.
// ---------------------------------------------------------------------------
__global__ __launch_bounds__(128) void proj_kernel(
    const float* __restrict__ x,
    const float* __restrict__ Wf, const float* __restrict__ bf,
    const float* __restrict__ Wg, const float* __restrict__ bg,
    const float* __restrict__ Wh, const float* __restrict__ bh)
{
    __shared__ __align__(16) float xs[64][68];
    __shared__ __align__(16) float WhT[64][68];
    __shared__ __align__(16) float WfT[8][68];
    __shared__ __align__(16) float WgT[8][68];
    __shared__ float bias[64];

    const int tid = threadIdx.x;
    const int rowbase = blockIdx.x * 64;

    for (int i = tid; i < 1024; i += 128) {
        const int r = i >> 4, c4 = i & 15;
        *(float4*)&xs[r][c4 * 4] = ((const float4*)(x + (size_t)rowbase * CDIM))[i];
    }
    for (int i = tid; i < 4096; i += 128)
        WhT[i & 63][i >> 6] = Wh[i];
    for (int i = tid; i < 512; i += 128) {
        WfT[i & 7][i >> 3] = Wf[i];
        WgT[i & 7][i >> 3] = Wg[i];
    }
    if (tid < 64) bias[tid] = bh[tid];
    __syncthreads();

    const int rloc = (tid & 31) | ((tid >> 6) << 5);   // 0..63
    const int half = (tid >> 5) & 1;
    const int row  = rowbase + rloc;
    const int b    = row >> 12;
    const int nl   = row & (NTOK - 1);
    const int key  = nl & 31;
    const int nlp  = (nl & ~31) | vperm(key);

    float xr[64];
#pragma unroll
    for (int c4 = 0; c4 < 16; c4++) {
        const float4 t = *(const float4*)&xs[rloc][c4 * 4];
        xr[c4 * 4 + 0] = t.x; xr[c4 * 4 + 1] = t.y;
        xr[c4 * 4 + 2] = t.z; xr[c4 * 4 + 3] = t.w;
    }

    // v: my 32-channel half, bf16, channel-major, key-permuted
#pragma unroll 1
    for (int ch = half * 32; ch < half * 32 + 32; ch++) {
        const float4* w = (const float4*)&WhT[ch][0];
        float a0 = 0.f, a1 = 0.f, a2 = 0.f, a3 = 0.f;
#pragma unroll
        for (int c4 = 0; c4 < 16; c4 += 4) {
            float4 ww;
            ww = w[c4];
            a0 += xr[c4*4+0]*ww.x + xr[c4*4+1]*ww.y + xr[c4*4+2]*ww.z + xr[c4*4+3]*ww.w;
            ww = w[c4+1];
            a1 += xr[c4*4+4]*ww.x + xr[c4*4+5]*ww.y + xr[c4*4+6]*ww.z + xr[c4*4+7]*ww.w;
            ww = w[c4+2];
            a2 += xr[c4*4+8]*ww.x + xr[c4*4+9]*ww.y + xr[c4*4+10]*ww.z + xr[c4*4+11]*ww.w;
            ww = w[c4+3];
            a3 += xr[c4*4+12]*ww.x + xr[c4*4+13]*ww.y + xr[c4*4+14]*ww.z + xr[c4*4+15]*ww.w;
        }
        const float a = bias[ch] + ((a0 + a1) + (a2 + a3));
        g_vb[((size_t)b * CDIM + ch) * NTOK + nlp] = __float2bfloat16_rn(a);
    }

    if (half == 0) {
        float q8[8];
#pragma unroll
        for (int ch = 0; ch < DDIM; ch++) {
            const float4* w = (const float4*)&WfT[ch][0];
            float a0 = 0.f, a1 = 0.f;
#pragma unroll
            for (int c4 = 0; c4 < 16; c4 += 2) {
                float4 ww;
                ww = w[c4];
                a0 += xr[c4*4+0]*ww.x + xr[c4*4+1]*ww.y + xr[c4*4+2]*ww.z + xr[c4*4+3]*ww.w;
                ww = w[c4+1];
                a1 += xr[c4*4+4]*ww.x + xr[c4*4+5]*ww.y + xr[c4*4+6]*ww.z + xr[c4*4+7]*ww.w;
            }
            q8[ch] = LOG2E * (__ldg(&bf[ch]) + a0 + a1);
        }
        float* qdst = g_q + (size_t)row * DDIM;
        *(float4*)qdst       = make_float4(q8[0], q8[1], q8[2], q8[3]);
        *(float4*)(qdst + 4) = make_float4(q8[4], q8[5], q8[6], q8[7]);
    } else {
        float k8[8];
#pragma unroll
        for (int ch = 0; ch < DDIM; ch++) {
            const float4* w = (const float4*)&WgT[ch][0];
            float a0 = 0.f, a1 = 0.f;
#pragma unroll
            for (int c4 = 0; c4 < 16; c4 += 2) {
                float4 ww;
                ww = w[c4];
                a0 += xr[c4*4+0]*ww.x + xr[c4*4+1]*ww.y + xr[c4*4+2]*ww.z + xr[c4*4+3]*ww.w;
                ww = w[c4+1];
                a1 += xr[c4*4+4]*ww.x + xr[c4*4+5]*ww.y + xr[c4*4+6]*ww.z + xr[c4*4+7]*ww.w;
            }
            k8[ch] = __ldg(&bg[ch]) + a0 + a1;
        }
        u32 kw[8];
#pragma unroll
        for (int t = 0; t < 4; t++) {
            const float b0 = __bfloat162float(__float2bfloat16_rn(k8[2 * t]));
            const float b1 = __bfloat162float(__float2bfloat16_rn(k8[2 * t + 1]));
            kw[2 * t]     = pack_bf16(b1, b0);
            kw[2 * t + 1] = pack_bf16(k8[2 * t + 1] - b1, k8[2 * t] - b0);
        }
        uint4* kd = (uint4*)&g_kp[(size_t)row * 8];
        kd[0] = make_uint4(kw[0], kw[1], kw[2], kw[3]);
        kd[1] = make_uint4(kw[4], kw[5], kw[6], kw[7]);
    }
}

// ---------------------------------------------------------------------------
// Attention: 512 threads = 2 split-K groups of 256, double-buffered 64-key
// tiles (two 32-key blocks), ONE group barrier per tile. Compute per 32-key
// block identical to R8 (QK via bf16-split mma, ex2 into PV A-frags, PV via
// bf16 mma). Epilogue osm/lsm aliases the K/V pool (separated by syncthreads).
// ---------------------------------------------------------------------------
__global__ __launch_bounds__(512, 1) void attn_kernel(
    const float* __restrict__ x,
    const float* __restrict__ gamma_p,
    float* __restrict__ out)
{
    // pool: Kc[grp][buf][blk][256] (8KB) then Vs[grp][buf][blk][1024] (32KB)
    __shared__ __align__(16) u32 SM[10240];

    const int tid  = threadIdx.x;
    const int grp  = tid >> 8;
    const int lt   = tid & 255;
    const int warp = lt >> 5;
    const int lane = tid & 31;
    const int g    = lane >> 2;
    const int t4   = lane & 3;
    const int bid  = blockIdx.y;
    const int q0   = blockIdx.x * QB;
    const int barid = grp + 1;

#define KCP(gr, bu, bl) (SM + (((gr) * 2 + (bu)) * 2 + (bl)) * 256)
#define VSP(gr, bu, bl) (SM + 2048 + (((gr) * 2 + (bu)) * 2 + (bl)) * 1024)

    const int rA_l = warp * 16 + g;
    const int rB_l = rA_l + 8;
    const int rowA = q0 + rA_l;
    const int rowB = q0 + rB_l;

    u32 QA0, QA1, QA2, QA3;
    {
        const float2 qA = *(const float2*)(g_q + ((size_t)bid * NTOK + rowA) * DDIM + 2 * t4);
        const float2 qB = *(const float2*)(g_q + ((size_t)bid * NTOK + rowB) * DDIM + 2 * t4);
        const float bAx = __bfloat162float(__float2bfloat16_rn(qA.x));
        const float bAy = __bfloat162float(__float2bfloat16_rn(qA.y));
        const float bBx = __bfloat162float(__float2bfloat16_rn(qB.x));
        const float bBy = __bfloat162float(__float2bfloat16_rn(qB.y));
        QA0 = pack_bf16(bAy, bAx);
        QA1 = pack_bf16(bBy, bBx);
        QA2 = pack_bf16(qA.y - bAy, qA.x - bAx);
        QA3 = pack_bf16(qB.y - bBy, qB.x - bBx);
    }

    float o[8][4];
#pragma unroll
    for (int n = 0; n < 8; n++)
#pragma unroll
        for (int r = 0; r < 4; r++) o[n][r] = 0.0f;
    float la0 = 0.0f, la1 = 0.0f, lb0 = 0.0f, lb1 = 0.0f;

    const u32* kpbase = g_kp + (size_t)bid * NTOK * 8;
    const __nv_bfloat16* vbbase = g_vb + (size_t)bid * CDIM * NTOK;

    const int NIT = 32;                 // 64-key tiles per group
    const int kbase0 = grp * (NIT * 64);

    uint4 kpre;                         // lt<128: one uint4 of K (blk = lt>>6)
    uint4 vpre0, vpre1;                 // V: blk0, blk1
    const int vch  = lt >> 2;           // 0..63
    const int vchk = lt & 3;            // 16B chunk within 64B row-half

    // ---- prologue: tile 0 -> buf0, tile 1 -> regs ----
    {
        const int k0 = kbase0;
        if (lt < 128) {
            kpre = ((const uint4*)(kpbase + (size_t)k0 * 8))[lt];
            ((uint4*)KCP(grp, 0, lt >> 6))[lt & 63] = kpre;
        }
        vpre0 = *(const uint4*)((const char*)(vbbase + (size_t)vch * NTOK + k0) + vchk * 16);
        vpre1 = *(const uint4*)((const char*)(vbbase + (size_t)vch * NTOK + k0 + 32) + vchk * 16);
        ((uint4*)VSP(grp, 0, 0))[vch * 4 + vchk] = vpre0;
        ((uint4*)VSP(grp, 0, 1))[vch * 4 + vchk] = vpre1;
        const int k1 = kbase0 + 64;
        if (lt < 128) kpre = ((const uint4*)(kpbase + (size_t)k1 * 8))[lt];
        vpre0 = *(const uint4*)((const char*)(vbbase + (size_t)vch * NTOK + k1) + vchk * 16);
        vpre1 = *(const uint4*)((const char*)(vbbase + (size_t)vch * NTOK + k1 + 32) + vchk * 16);
    }
    GBAR(barid);

    for (int i = 0; i < NIT; i++) {
        const int buf = i & 1;
        const int nbuf = buf ^ 1;

        // ---- store tile i+1 into the idle buffer ----
        if (i + 1 < NIT) {
            if (lt < 128) ((uint4*)KCP(grp, nbuf, lt >> 6))[lt & 63] = kpre;
            ((uint4*)VSP(grp, nbuf, 0))[vch * 4 + vchk] = vpre0;
            ((uint4*)VSP(grp, nbuf, 1))[vch * 4 + vchk] = vpre1;
        }
        // ---- issue loads for tile i+2 ----
        if (i + 2 < NIT) {
            const int k0 = kbase0 + (i + 2) * 64;
            if (lt < 128) kpre = ((const uint4*)(kpbase + (size_t)k0 * 8))[lt];
            vpre0 = *(const uint4*)((const char*)(vbbase + (size_t)vch * NTOK + k0) + vchk * 16);
            vpre1 = *(const uint4*)((const char*)(vbbase + (size_t)vch * NTOK + k0 + 32) + vchk * 16);
        }

        // ---- compute both 32-key blocks of tile i from buf ----
#pragma unroll
        for (int blk = 0; blk < 2; blk++) {
            const u32* kc = KCP(grp, buf, blk);
            const u32* vs = VSP(grp, buf, blk);

            float d[4][4];
#pragma unroll
            for (int nt = 0; nt < 4; nt++) {
                const uint2 kk = *(const uint2*)&kc[(nt * 8 + g) * 8 + t4 * 2];
                mma_bf16_z(d[nt], QA0, QA1, QA2, QA3, kk.x, kk.y);
                mma_bf16 (d[nt], QA0, QA1, QA2, QA3, kk.y, kk.x);
            }

            u32 pf[2][4];
#pragma unroll
            for (int s = 0; s < 2; s++) {
                const float eA0 = ex2f(d[2 * s][0]),     eA1 = ex2f(d[2 * s][1]);
                const float eB0 = ex2f(d[2 * s][2]),     eB1 = ex2f(d[2 * s][3]);
                const float fA0 = ex2f(d[2 * s + 1][0]), fA1 = ex2f(d[2 * s + 1][1]);
                const float fB0 = ex2f(d[2 * s + 1][2]), fB1 = ex2f(d[2 * s + 1][3]);
                la0 += eA0 + eA1;  la1 += fA0 + fA1;
                lb0 += eB0 + eB1;  lb1 += fB0 + fB1;
                pf[s][0] = pack_bf16(eA1, eA0);
                pf[s][1] = pack_bf16(eB1, eB0);
                pf[s][2] = pack_bf16(fA1, fA0);
                pf[s][3] = pack_bf16(fB1, fB0);
            }

#pragma unroll
            for (int n = 0; n < 8; n++) {
                const uint4 vv = *(const uint4*)&vs[(n * 8 + g) * 16 + t4 * 4];
                mma_bf16(o[n], pf[0][0], pf[0][1], pf[0][2], pf[0][3], vv.x, vv.y);
                mma_bf16(o[n], pf[1][0], pf[1][1], pf[1][2], pf[1][3], vv.z, vv.w);
            }
        }
        GBAR(barid);
    }

    float la = la0 + la1;
    float lb = lb0 + lb1;
    la += __shfl_xor_sync(0xffffffffu, la, 1);
    la += __shfl_xor_sync(0xffffffffu, la, 2);
    lb += __shfl_xor_sync(0xffffffffu, lb, 1);
    lb += __shfl_xor_sync(0xffffffffu, lb, 2);

    // both groups must be fully done with Kc/Vs before osm/lsm (aliased) use
    __syncthreads();

    float* osm = (float*)SM;                 // [128][34]
    float* lsm = (float*)SM + QB * 34;       // [128]

#pragma unroll
    for (int h = 0; h < 2; h++) {
        if (grp == 1) {
            if (h == 0 && t4 == 0) {
                lsm[rA_l] = la;
                lsm[rB_l] = lb;
            }
#pragma unroll
            for (int n = h * 4; n < h * 4 + 4; n++) {
                const int col = (n * 8 + 2 * t4) & 31;
                *(float2*)&osm[rA_l * 34 + col] = make_float2(o[n][0], o[n][1]);
                *(float2*)&osm[rB_l * 34 + col] = make_float2(o[n][2], o[n][3]);
            }
        }
        __syncthreads();
        if (grp == 0) {
            if (h == 0) { la += lsm[rA_l]; lb += lsm[rB_l]; }
#pragma unroll
            for (int n = h * 4; n < h * 4 + 4; n++) {
                const int col = (n * 8 + 2 * t4) & 31;
                const float2 ea = *(const float2*)&osm[rA_l * 34 + col];
                const float2 eb = *(const float2*)&osm[rB_l * 34 + col];
                o[n][0] += ea.x; o[n][1] += ea.y;
                o[n][2] += eb.x; o[n][3] += eb.y;
            }
        }
        __syncthreads();
    }

    if (grp == 0) {
        const float gamma = *gamma_p;
        const float gia = gamma / la;
        const float gib = gamma / lb;
        const size_t baseA = ((size_t)bid * NTOK + rowA) * CDIM;
        const size_t baseB = ((size_t)bid * NTOK + rowB) * CDIM;
#pragma unroll
        for (int n = 0; n < 8; n++) {
            const int col = n * 8 + 2 * t4;
            const float2 xvA = *(const float2*)&x[baseA + col];
            const float2 xvB = *(const float2*)&x[baseB + col];
            float2 ovA, ovB;
            ovA.x = gia * o[n][0] + xvA.x;
            ovA.y = gia * o[n][1] + xvA.y;
            ovB.x = gib * o[n][2] + xvB.x;
            ovB.y = gib * o[n][3] + xvB.y;
            *(float2*)&out[baseA + col] = ovA;
            *(float2*)&out[baseB + col] = ovB;
        }
    }
}

extern "C" void kernel_launch(void* const* d_in, const int* in_sizes, int n_in,
                              void* d_out, int out_size)
{
    const float* x     = (const float*)d_in[0];
    const float* Wf    = (const float*)d_in[1];
    const float* bf    = (const float*)d_in[2];
    const float* Wg    = (const float*)d_in[3];
    const float* bg    = (const float*)d_in[4];
    const float* Wh    = (const float*)d_in[5];
    const float* bh    = (const float*)d_in[6];
    const float* gamma = (const float*)d_in[7];
    float* out = (float*)d_out;

    proj_kernel<<<(BATCH * NTOK) / 64, 128>>>(x, Wf, bf, Wg, bg, Wh, bh);
    attn_kernel<<<dim3(NTOK / QB, BATCH), 512>>>(x, gamma, out);
}

// round 15
// speedup vs baseline: 1.0428x; 1.0428x over previous
#include <cuda_runtime.h>
#include <cuda_bf16.h>
#include <cstdint>

#define BATCH 4
#define NTOK 4096        // H*W
#define CDIM 64
#define DDIM 8
#define KT 32            // keys per tile
#define NT (NTOK / KT)   // 128 tiles
#define QB 64            // queries per CTA
#define LOG2E 1.4426950408889634f

typedef unsigned int u32;

// group barrier: 128 threads, barrier id 1 or 2
#define GBAR(id) asm volatile("bar.sync %0, %1;" :: "r"(id), "r"(128) : "memory")

#define CP_COMMIT() asm volatile("cp.async.commit_group;" ::: "memory")
#define CP_WAIT1()  asm volatile("cp.async.wait_group 1;" ::: "memory")

__device__ __forceinline__ void cp16(u32 dst, const void* src) {
    asm volatile("cp.async.cg.shared.global [%0], [%1], 16;" :: "r"(dst), "l"(src));
}
__device__ __forceinline__ u32 smem_addr(const void* p) {
    return (u32)__cvta_generic_to_shared(p);
}
__device__ __forceinline__ float ex2f(float x) {
    float r;
    asm("ex2.approx.f32 %0, %1;" : "=f"(r) : "f"(x));
    return r;
}
__device__ __forceinline__ u32 pack_bf16(float hi, float lo) {
    u32 r;
    asm("cvt.rn.bf16x2.f32 %0, %1, %2;" : "=r"(r) : "f"(hi), "f"(lo));
    return r;
}

__device__ __forceinline__ void mma_bf16(float* d,
                                         u32 a0, u32 a1, u32 a2, u32 a3,
                                         u32 b0, u32 b1) {
    asm("mma.sync.aligned.m16n8k16.row.col.f32.bf16.bf16.f32 "
        "{%0,%1,%2,%3}, {%4,%5,%6,%7}, {%8,%9}, {%0,%1,%2,%3};"
        : "+f"(d[0]), "+f"(d[1]), "+f"(d[2]), "+f"(d[3])
        : "r"(a0), "r"(a1), "r"(a2), "r"(a3), "r"(b0), "r"(b1));
}
__device__ __forceinline__ void mma_bf16_z(float* d,
                                           u32 a0, u32 a1, u32 a2, u32 a3,
                                           u32 b0, u32 b1) {
    asm("mma.sync.aligned.m16n8k16.row.col.f32.bf16.bf16.f32 "
        "{%0,%1,%2,%3}, {%4,%5,%6,%7}, {%8,%9}, {%10,%11,%12,%13};"
        : "=f"(d[0]), "=f"(d[1]), "=f"(d[2]), "=f"(d[3])
        : "r"(a0), "r"(a1), "r"(a2), "r"(a3), "r"(b0), "r"(b1),
          "f"(0.0f), "f"(0.0f), "f"(0.0f), "f"(0.0f));
}

// ---------------- scratch ----------------
__device__ float g_q[BATCH * NTOK * DDIM];            // fp32 q, pre-scaled by log2(e)
__device__ u32 g_kp[BATCH * NTOK * 8];                // bf16 split k, packed per key
__device__ __nv_bfloat16 g_vb[(size_t)BATCH * CDIM * NTOK];  // bf16 v, ch-major, key-permuted

// position of key j (0..31) within its 32-block in g_vb / Vs
__device__ __forceinline__ int vperm(int j) {
    const int blk = j >> 4;
    const int k   = j & 15;
    const int rho = 4 * ((k >> 1) & 3) + (k & 1) + 2 * (k >> 3);
    return (rho >> 2) * 8 + blk * 4 + (rho & 3);
}

// ---------------------------------------------------------------------------
// Projection (identical to R8). 128 threads, 64 rows/CTA, 2 threads/row.
// ---------------------------------------------------------------------------
__global__ __launch_bounds__(128) void proj_kernel(
    const float* __restrict__ x,
    const float* __restrict__ Wf, const float* __restrict__ bf,
    const float* __restrict__ Wg, const float* __restrict__ bg,
    const float* __restrict__ Wh, const float* __restrict__ bh)
{
    __shared__ __align__(16) float xs[64][68];
    __shared__ __align__(16) float WhT[64][68];
    __shared__ __align__(16) float WfT[8][68];
    __shared__ __align__(16) float WgT[8][68];
    __shared__ float bias[64];

    const int tid = threadIdx.x;
    const int rowbase = blockIdx.x * 64;

    for (int i = tid; i < 1024; i += 128) {
        const int r = i >> 4, c4 = i & 15;
        *(float4*)&xs[r][c4 * 4] = ((const float4*)(x + (size_t)rowbase * CDIM))[i];
    }
    for (int i = tid; i < 4096; i += 128)
        WhT[i & 63][i >> 6] = Wh[i];
    for (int i = tid; i < 512; i += 128) {
        WfT[i & 7][i >> 3] = Wf[i];
        WgT[i & 7][i >> 3] = Wg[i];
    }
    if (tid < 64) bias[tid] = bh[tid];
    __syncthreads();

    const int rloc = (tid & 31) | ((tid >> 6) << 5);   // 0..63
    const int half = (tid >> 5) & 1;
    const int row  = rowbase + rloc;
    const int b    = row >> 12;
    const int nl   = row & (NTOK - 1);
    const int key  = nl & 31;
    const int nlp  = (nl & ~31) | vperm(key);

    float xr[64];
#pragma unroll
    for (int c4 = 0; c4 < 16; c4++) {
        const float4 t = *(const float4*)&xs[rloc][c4 * 4];
        xr[c4 * 4 + 0] = t.x; xr[c4 * 4 + 1] = t.y;
        xr[c4 * 4 + 2] = t.z; xr[c4 * 4 + 3] = t.w;
    }

#pragma unroll 1
    for (int ch = half * 32; ch < half * 32 + 32; ch++) {
        const float4* w = (const float4*)&WhT[ch][0];
        float a0 = 0.f, a1 = 0.f, a2 = 0.f, a3 = 0.f;
#pragma unroll
        for (int c4 = 0; c4 < 16; c4 += 4) {
            float4 ww;
            ww = w[c4];
            a0 += xr[c4*4+0]*ww.x + xr[c4*4+1]*ww.y + xr[c4*4+2]*ww.z + xr[c4*4+3]*ww.w;
            ww = w[c4+1];
            a1 += xr[c4*4+4]*ww.x + xr[c4*4+5]*ww.y + xr[c4*4+6]*ww.z + xr[c4*4+7]*ww.w;
            ww = w[c4+2];
            a2 += xr[c4*4+8]*ww.x + xr[c4*4+9]*ww.y + xr[c4*4+10]*ww.z + xr[c4*4+11]*ww.w;
            ww = w[c4+3];
            a3 += xr[c4*4+12]*ww.x + xr[c4*4+13]*ww.y + xr[c4*4+14]*ww.z + xr[c4*4+15]*ww.w;
        }
        const float a = bias[ch] + ((a0 + a1) + (a2 + a3));
        g_vb[((size_t)b * CDIM + ch) * NTOK + nlp] = __float2bfloat16_rn(a);
    }

    if (half == 0) {
        float q8[8];
#pragma unroll
        for (int ch = 0; ch < DDIM; ch++) {
            const float4* w = (const float4*)&WfT[ch][0];
            float a0 = 0.f, a1 = 0.f;
#pragma unroll
            for (int c4 = 0; c4 < 16; c4 += 2) {
                float4 ww;
                ww = w[c4];
                a0 += xr[c4*4+0]*ww.x + xr[c4*4+1]*ww.y + xr[c4*4+2]*ww.z + xr[c4*4+3]*ww.w;
                ww = w[c4+1];
                a1 += xr[c4*4+4]*ww.x + xr[c4*4+5]*ww.y + xr[c4*4+6]*ww.z + xr[c4*4+7]*ww.w;
            }
            q8[ch] = LOG2E * (__ldg(&bf[ch]) + a0 + a1);
        }
        float* qdst = g_q + (size_t)row * DDIM;
        *(float4*)qdst       = make_float4(q8[0], q8[1], q8[2], q8[3]);
        *(float4*)(qdst + 4) = make_float4(q8[4], q8[5], q8[6], q8[7]);
    } else {
        float k8[8];
#pragma unroll
        for (int ch = 0; ch < DDIM; ch++) {
            const float4* w = (const float4*)&WgT[ch][0];
            float a0 = 0.f, a1 = 0.f;
#pragma unroll
            for (int c4 = 0; c4 < 16; c4 += 2) {
                float4 ww;
                ww = w[c4];
                a0 += xr[c4*4+0]*ww.x + xr[c4*4+1]*ww.y + xr[c4*4+2]*ww.z + xr[c4*4+3]*ww.w;
                ww = w[c4+1];
                a1 += xr[c4*4+4]*ww.x + xr[c4*4+5]*ww.y + xr[c4*4+6]*ww.z + xr[c4*4+7]*ww.w;
            }
            k8[ch] = __ldg(&bg[ch]) + a0 + a1;
        }
        u32 kw[8];
#pragma unroll
        for (int t = 0; t < 4; t++) {
            const float b0 = __bfloat162float(__float2bfloat16_rn(k8[2 * t]));
            const float b1 = __bfloat162float(__float2bfloat16_rn(k8[2 * t + 1]));
            kw[2 * t]     = pack_bf16(b1, b0);
            kw[2 * t + 1] = pack_bf16(k8[2 * t + 1] - b1, k8[2 * t] - b0);
        }
        uint4* kd = (uint4*)&g_kp[(size_t)row * 8];
        kd[0] = make_uint4(kw[0], kw[1], kw[2], kw[3]);
        kd[1] = make_uint4(kw[4], kw[5], kw[6], kw[7]);
    }
}

// ---------------------------------------------------------------------------
// Attention: QB=64, 256 threads = 2 split-K groups of 128 (4 warps x 16 q).
// 2 CTAs/SM (launch_bounds 256,2): grid 256 covers all 148 SMs. K/V staged
// via cp.async into double buffers; math identical to R8 (bf16 split QK,
// f32 ex2 into bf16 PV A-frags, f32 accum; o/l linear, merge at end).
// ---------------------------------------------------------------------------
__global__ __launch_bounds__(256, 2) void attn_kernel(
    const float* __restrict__ x,
    const float* __restrict__ gamma_p,
    float* __restrict__ out)
{
    __shared__ __align__(16) u32 Kc[2][2][KT * 8];     // [grp][buf] 4 KB total
    __shared__ __align__(16) u32 Vs[2][2][CDIM * 16];  // [grp][buf] 16 KB total
    __shared__ __align__(16) float osm[QB][34];        // 8.5 KB
    __shared__ float lsm[QB];

    const int tid  = threadIdx.x;
    const int grp  = tid >> 7;        // 0 or 1
    const int lt   = tid & 127;       // thread within group
    const int warp = lt >> 5;         // 0..3
    const int lane = tid & 31;
    const int g    = lane >> 2;
    const int t4   = lane & 3;
    const int bid  = blockIdx.y;
    const int q0   = blockIdx.x * QB;
    const int barid = grp + 1;

    const int rA_l = warp * 16 + g;   // 0..63
    const int rB_l = rA_l + 8;
    const int rowA = q0 + rA_l;
    const int rowB = q0 + rB_l;

    // QK A-frags (bf16 split)
    u32 QA0, QA1, QA2, QA3;
    {
        const float2 qA = *(const float2*)(g_q + ((size_t)bid * NTOK + rowA) * DDIM + 2 * t4);
        const float2 qB = *(const float2*)(g_q + ((size_t)bid * NTOK + rowB) * DDIM + 2 * t4);
        const float bAx = __bfloat162float(__float2bfloat16_rn(qA.x));
        const float bAy = __bfloat162float(__float2bfloat16_rn(qA.y));
        const float bBx = __bfloat162float(__float2bfloat16_rn(qB.x));
        const float bBy = __bfloat162float(__float2bfloat16_rn(qB.y));
        QA0 = pack_bf16(bAy, bAx);
        QA1 = pack_bf16(bBy, bBx);
        QA2 = pack_bf16(qA.y - bAy, qA.x - bAx);
        QA3 = pack_bf16(qB.y - bBy, qB.x - bBx);
    }

    float o[8][4];
#pragma unroll
    for (int n = 0; n < 8; n++)
#pragma unroll
        for (int r = 0; r < 4; r++) o[n][r] = 0.0f;
    float la0 = 0.0f, la1 = 0.0f, lb0 = 0.0f, lb1 = 0.0f;

    const u32* kpbase = g_kp + (size_t)bid * NTOK * 8;
    const __nv_bfloat16* vbbase = g_vb + (size_t)bid * CDIM * NTOK;

    const int t0 = grp * (NT / 2);
    const int t1 = t0 + (NT / 2);

    // cp.async loaders: K = 64 uint4 (lt<64, 1 each); V = 256 uint4 (2 each)
    const int vi0 = lt,        vch0 = vi0 >> 2, vk0 = vi0 & 3;
    const int vi1 = lt + 128,  vch1 = vi1 >> 2, vk1 = vi1 & 3;

#define ISSUE_TILE(tt, bu) do { \
        const int _k0 = (tt) * KT; \
        if (lt < 64) \
            cp16(smem_addr(&Kc[grp][bu][lt * 4]), kpbase + (size_t)_k0 * 8 + lt * 4); \
        cp16(smem_addr(&Vs[grp][bu][vch0 * 16 + vk0 * 4]), \
             (const char*)(vbbase + (size_t)vch0 * NTOK + _k0) + vk0 * 16); \
        cp16(smem_addr(&Vs[grp][bu][vch1 * 16 + vk1 * 4]), \
             (const char*)(vbbase + (size_t)vch1 * NTOK + _k0) + vk1 * 16); \
        CP_COMMIT(); \
    } while (0)

    // prologue: tiles t0 -> buf0, t0+1 -> buf1
    ISSUE_TILE(t0, 0);
    ISSUE_TILE(t0 + 1, 1);

    for (int t = t0; t < t1; t++) {
        const int buf = t & 1;
        CP_WAIT1();                 // tile t landed (<=1 younger group pending)
        GBAR(barid);                // visible to whole group

        const u32* kc = Kc[grp][buf];
        const u32* vs = Vs[grp][buf];

        // ---- QK: 4 n-tiles x 2 bf16-split mmas (exact to ~2^-17) ----
        float d[4][4];
#pragma unroll
        for (int nt = 0; nt < 4; nt++) {
            const uint2 kk = *(const uint2*)&kc[(nt * 8 + g) * 8 + t4 * 2];
            mma_bf16_z(d[nt], QA0, QA1, QA2, QA3, kk.x, kk.y);  // Qb.kb + Qd.kd
            mma_bf16 (d[nt], QA0, QA1, QA2, QA3, kk.y, kk.x);   // Qb.kd + Qd.kb
        }

        // ---- f32 exp2 + l + pack into PV A-frags (bf16x2) ----
        u32 pf[2][4];
#pragma unroll
        for (int s = 0; s < 2; s++) {
            const float eA0 = ex2f(d[2 * s][0]),     eA1 = ex2f(d[2 * s][1]);
            const float eB0 = ex2f(d[2 * s][2]),     eB1 = ex2f(d[2 * s][3]);
            const float fA0 = ex2f(d[2 * s + 1][0]), fA1 = ex2f(d[2 * s + 1][1]);
            const float fB0 = ex2f(d[2 * s + 1][2]), fB1 = ex2f(d[2 * s + 1][3]);
            la0 += eA0 + eA1;  la1 += fA0 + fA1;
            lb0 += eB0 + eB1;  lb1 += fB0 + fB1;
            pf[s][0] = pack_bf16(eA1, eA0);
            pf[s][1] = pack_bf16(eB1, eB0);
            pf[s][2] = pack_bf16(fA1, fA0);
            pf[s][3] = pack_bf16(fB1, fB0);
        }

        // ---- P x V: 8 n-tiles x 2 k-steps, B-frags one LDS.128 per n ----
#pragma unroll
        for (int n = 0; n < 8; n++) {
            const uint4 vv = *(const uint4*)&vs[(n * 8 + g) * 16 + t4 * 4];
            mma_bf16(o[n], pf[0][0], pf[0][1], pf[0][2], pf[0][3], vv.x, vv.y);
            mma_bf16(o[n], pf[1][0], pf[1][1], pf[1][2], pf[1][3], vv.z, vv.w);
        }

        GBAR(barid);                // whole group done reading buf
        if (t + 2 < t1) ISSUE_TILE(t + 2, buf);
    }

    float la = la0 + la1;
    float lb = lb0 + lb1;
    la += __shfl_xor_sync(0xffffffffu, la, 1);
    la += __shfl_xor_sync(0xffffffffu, la, 2);
    lb += __shfl_xor_sync(0xffffffffu, lb, 1);
    lb += __shfl_xor_sync(0xffffffffu, lb, 2);

    // ---- merge split-K partials ----
#pragma unroll
    for (int h = 0; h < 2; h++) {
        if (grp == 1) {
            if (h == 0 && t4 == 0) {
                lsm[rA_l] = la;
                lsm[rB_l] = lb;
            }
#pragma unroll
            for (int n = h * 4; n < h * 4 + 4; n++) {
                const int col = (n * 8 + 2 * t4) & 31;
                *(float2*)&osm[rA_l][col] = make_float2(o[n][0], o[n][1]);
                *(float2*)&osm[rB_l][col] = make_float2(o[n][2], o[n][3]);
            }
        }
        __syncthreads();
        if (grp == 0) {
            if (h == 0) { la += lsm[rA_l]; lb += lsm[rB_l]; }
#pragma unroll
            for (int n = h * 4; n < h * 4 + 4; n++) {
                const int col = (n * 8 + 2 * t4) & 31;
                const float2 ea = *(const float2*)&osm[rA_l][col];
                const float2 eb = *(const float2*)&osm[rB_l][col];
                o[n][0] += ea.x; o[n][1] += ea.y;
                o[n][2] += eb.x; o[n][3] += eb.y;
            }
        }
        __syncthreads();
    }

    if (grp == 0) {
        const float gamma = *gamma_p;
        const float gia = gamma / la;
        const float gib = gamma / lb;
        const size_t baseA = ((size_t)bid * NTOK + rowA) * CDIM;
        const size_t baseB = ((size_t)bid * NTOK + rowB) * CDIM;
#pragma unroll
        for (int n = 0; n < 8; n++) {
            const int col = n * 8 + 2 * t4;
            const float2 xvA = *(const float2*)&x[baseA + col];
            const float2 xvB = *(const float2*)&x[baseB + col];
            float2 ovA, ovB;
            ovA.x = gia * o[n][0] + xvA.x;
            ovA.y = gia * o[n][1] + xvA.y;
            ovB.x = gib * o[n][2] + xvB.x;
            ovB.y = gib * o[n][3] + xvB.y;
            *(float2*)&out[baseA + col] = ovA;
            *(float2*)&out[baseB + col] = ovB;
        }
    }
}

extern "C" void kernel_launch(void* const* d_in, const int* in_sizes, int n_in,
                              void* d_out, int out_size)
{
    const float* x     = (const float*)d_in[0];
    const float* Wf    = (const float*)d_in[1];
    const float* bf    = (const float*)d_in[2];
    const float* Wg    = (const float*)d_in[3];
    const float* bg    = (const float*)d_in[4];
    const float* Wh    = (const float*)d_in[5];
    const float* bh    = (const float*)d_in[6];
    const float* gamma = (const float*)d_in[7];
    float* out = (float*)d_out;

    proj_kernel<<<(BATCH * NTOK) / 64, 128>>>(x, Wf, bf, Wg, bg, Wh, bh);
    attn_kernel<<<dim3(NTOK / QB, BATCH), 256>>>(x, gamma, out);
}

// round 16
// speedup vs baseline: 1.0785x; 1.0343x over previous
#include <cuda_runtime.h>
#include <cuda_bf16.h>
#include <cstdint>

#define BATCH 4
#define NTOK 4096        // H*W
#define CDIM 64
#define DDIM 8
#define KT 32            // keys per tile
#define NT (NTOK / KT)   // 128 tiles
#define QB 64            // queries per CTA
#define LOG2E 1.4426950408889634f

typedef unsigned int u32;

// group barrier: 128 threads, barrier id 1 or 2
#define GBAR(id) asm volatile("bar.sync %0, %1;" :: "r"(id), "r"(128) : "memory")

#define CP_COMMIT() asm volatile("cp.async.commit_group;" ::: "memory")
#define CP_WAIT1()  asm volatile("cp.async.wait_group 1;" ::: "memory")

__device__ __forceinline__ void cp16(u32 dst, const void* src) {
    asm volatile("cp.async.cg.shared.global [%0], [%1], 16;" :: "r"(dst), "l"(src));
}
__device__ __forceinline__ u32 smem_addr(const void* p) {
    return (u32)__cvta_generic_to_shared(p);
}
__device__ __forceinline__ float ex2f(float x) {
    float r;
    asm("ex2.approx.f32 %0, %1;" : "=f"(r) : "f"(x));
    return r;
}
__device__ __forceinline__ u32 pack_bf16(float hi, float lo) {
    u32 r;
    asm("cvt.rn.bf16x2.f32 %0, %1, %2;" : "=r"(r) : "f"(hi), "f"(lo));
    return r;
}

__device__ __forceinline__ void mma_bf16(float* d,
                                         u32 a0, u32 a1, u32 a2, u32 a3,
                                         u32 b0, u32 b1) {
    asm("mma.sync.aligned.m16n8k16.row.col.f32.bf16.bf16.f32 "
        "{%0,%1,%2,%3}, {%4,%5,%6,%7}, {%8,%9}, {%0,%1,%2,%3};"
        : "+f"(d[0]), "+f"(d[1]), "+f"(d[2]), "+f"(d[3])
        : "r"(a0), "r"(a1), "r"(a2), "r"(a3), "r"(b0), "r"(b1));
}
__device__ __forceinline__ void mma_bf16_z(float* d,
                                           u32 a0, u32 a1, u32 a2, u32 a3,
                                           u32 b0, u32 b1) {
    asm("mma.sync.aligned.m16n8k16.row.col.f32.bf16.bf16.f32 "
        "{%0,%1,%2,%3}, {%4,%5,%6,%7}, {%8,%9}, {%10,%11,%12,%13};"
        : "=f"(d[0]), "=f"(d[1]), "=f"(d[2]), "=f"(d[3])
        : "r"(a0), "r"(a1), "r"(a2), "r"(a3), "r"(b0), "r"(b1),
          "f"(0.0f), "f"(0.0f), "f"(0.0f), "f"(0.0f));
}

// ---------------- scratch ----------------
__device__ float g_q[BATCH * NTOK * DDIM];            // fp32 q, pre-scaled by log2(e)
__device__ u32 g_kp[BATCH * NTOK * 8];                // bf16 split k, packed per key
__device__ __nv_bfloat16 g_vb[(size_t)BATCH * CDIM * NTOK];  // bf16 v, ch-major, key-permuted

// position of key j (0..31) within its 32-block in g_vb / Vs
__device__ __forceinline__ int vperm(int j) {
    const int blk = j >> 4;
    const int k   = j & 15;
    const int rho = 4 * ((k >> 1) & 3) + (k & 1) + 2 * (k >> 3);
    return (rho >> 2) * 8 + blk * 4 + (rho & 3);
}

// ---------------------------------------------------------------------------
// Projection — exact R8 version (serial accumulation; measured residual 7.3us).
// 128 threads, 64 rows/CTA (2 threads per row: channel halves).
// ---------------------------------------------------------------------------
__global__ __launch_bounds__(128) void proj_kernel(
    const float* __restrict__ x,
    const float* __restrict__ Wf, const float* __restrict__ bf,
    const float* __restrict__ Wg, const float* __restrict__ bg,
    const float* __restrict__ Wh, const float* __restrict__ bh)
{
    __shared__ __align__(16) float xs[64][68];
    __shared__ __align__(16) float WhT[64][68];
    __shared__ __align__(16) float WfT[8][68];
    __shared__ __align__(16) float WgT[8][68];
    __shared__ float bias[64];

    const int tid = threadIdx.x;
    const int rowbase = blockIdx.x * 64;

    for (int i = tid; i < 1024; i += 128) {
        const int r = i >> 4, c4 = i & 15;
        *(float4*)&xs[r][c4 * 4] = ((const float4*)(x + (size_t)rowbase * CDIM))[i];
    }
    for (int i = tid; i < 4096; i += 128)
        WhT[i & 63][i >> 6] = Wh[i];
    for (int i = tid; i < 512; i += 128) {
        WfT[i & 7][i >> 3] = Wf[i];
        WgT[i & 7][i >> 3] = Wg[i];
    }
    if (tid < 64) bias[tid] = bh[tid];
    __syncthreads();

    const int rloc = (tid & 31) | ((tid >> 6) << 5);   // 0..63
    const int half = (tid >> 5) & 1;
    const int row  = rowbase + rloc;
    const int b    = row >> 12;
    const int nl   = row & (NTOK - 1);
    const int key  = nl & 31;
    const int nlp  = (nl & ~31) | vperm(key);

    float xr[64];
#pragma unroll
    for (int c4 = 0; c4 < 16; c4++) {
        const float4 t = *(const float4*)&xs[rloc][c4 * 4];
        xr[c4 * 4 + 0] = t.x; xr[c4 * 4 + 1] = t.y;
        xr[c4 * 4 + 2] = t.z; xr[c4 * 4 + 3] = t.w;
    }

    // v: my 32-channel half, bf16, channel-major, key-permuted
#pragma unroll 1
    for (int ch = half * 32; ch < half * 32 + 32; ch++) {
        float a = bias[ch];
        const float4* w = (const float4*)&WhT[ch][0];
#pragma unroll
        for (int c4 = 0; c4 < 16; c4++) {
            const float4 ww = w[c4];
            a += xr[c4 * 4 + 0] * ww.x;
            a += xr[c4 * 4 + 1] * ww.y;
            a += xr[c4 * 4 + 2] * ww.z;
            a += xr[c4 * 4 + 3] * ww.w;
        }
        g_vb[((size_t)b * CDIM + ch) * NTOK + nlp] = __float2bfloat16_rn(a);
    }

    if (half == 0) {
        float q8[8];
#pragma unroll
        for (int ch = 0; ch < DDIM; ch++) {
            float a = __ldg(&bf[ch]);
            const float4* w = (const float4*)&WfT[ch][0];
#pragma unroll
            for (int c4 = 0; c4 < 16; c4++) {
                const float4 ww = w[c4];
                a += xr[c4 * 4 + 0] * ww.x;
                a += xr[c4 * 4 + 1] * ww.y;
                a += xr[c4 * 4 + 2] * ww.z;
                a += xr[c4 * 4 + 3] * ww.w;
            }
            q8[ch] = LOG2E * a;
        }
        float* qdst = g_q + (size_t)row * DDIM;
        *(float4*)qdst       = make_float4(q8[0], q8[1], q8[2], q8[3]);
        *(float4*)(qdst + 4) = make_float4(q8[4], q8[5], q8[6], q8[7]);
    } else {
        float k8[8];
#pragma unroll
        for (int ch = 0; ch < DDIM; ch++) {
            float a = __ldg(&bg[ch]);
            const float4* w = (const float4*)&WgT[ch][0];
#pragma unroll
            for (int c4 = 0; c4 < 16; c4++) {
                const float4 ww = w[c4];
                a += xr[c4 * 4 + 0] * ww.x;
                a += xr[c4 * 4 + 1] * ww.y;
                a += xr[c4 * 4 + 2] * ww.z;
                a += xr[c4 * 4 + 3] * ww.w;
            }
            k8[ch] = a;
        }
        u32 kw[8];
#pragma unroll
        for (int t = 0; t < 4; t++) {
            const float b0 = __bfloat162float(__float2bfloat16_rn(k8[2 * t]));
            const float b1 = __bfloat162float(__float2bfloat16_rn(k8[2 * t + 1]));
            kw[2 * t]     = pack_bf16(b1, b0);
            kw[2 * t + 1] = pack_bf16(k8[2 * t + 1] - b1, k8[2 * t] - b0);
        }
        uint4* kd = (uint4*)&g_kp[(size_t)row * 8];
        kd[0] = make_uint4(kw[0], kw[1], kw[2], kw[3]);
        kd[1] = make_uint4(kw[4], kw[5], kw[6], kw[7]);
    }
}

// ---------------------------------------------------------------------------
// Attention: QB=64, 256 threads = 2 split-K groups of 128, 2 CTAs/SM.
// Triple-buffered cp.async ring -> ONE group barrier per tile (write target
// of tile t+2 was last read at tile t-1, which every thread finished before
// tile t's barrier). Math identical to R8/R15.
// ---------------------------------------------------------------------------
__global__ __launch_bounds__(256, 2) void attn_kernel(
    const float* __restrict__ x,
    const float* __restrict__ gamma_p,
    float* __restrict__ out)
{
    __shared__ __align__(16) u32 Kc[2][3][KT * 8];     // [grp][buf] 6 KB
    __shared__ __align__(16) u32 Vs[2][3][CDIM * 16];  // [grp][buf] 24 KB
    __shared__ __align__(16) float osm[QB][34];        // 8.5 KB
    __shared__ float lsm[QB];

    const int tid  = threadIdx.x;
    const int grp  = tid >> 7;        // 0 or 1
    const int lt   = tid & 127;       // thread within group
    const int warp = lt >> 5;         // 0..3
    const int lane = tid & 31;
    const int g    = lane >> 2;
    const int t4   = lane & 3;
    const int bid  = blockIdx.y;
    const int q0   = blockIdx.x * QB;
    const int barid = grp + 1;

    const int rA_l = warp * 16 + g;   // 0..63
    const int rB_l = rA_l + 8;
    const int rowA = q0 + rA_l;
    const int rowB = q0 + rB_l;

    // QK A-frags (bf16 split)
    u32 QA0, QA1, QA2, QA3;
    {
        const float2 qA = *(const float2*)(g_q + ((size_t)bid * NTOK + rowA) * DDIM + 2 * t4);
        const float2 qB = *(const float2*)(g_q + ((size_t)bid * NTOK + rowB) * DDIM + 2 * t4);
        const float bAx = __bfloat162float(__float2bfloat16_rn(qA.x));
        const float bAy = __bfloat162float(__float2bfloat16_rn(qA.y));
        const float bBx = __bfloat162float(__float2bfloat16_rn(qB.x));
        const float bBy = __bfloat162float(__float2bfloat16_rn(qB.y));
        QA0 = pack_bf16(bAy, bAx);
        QA1 = pack_bf16(bBy, bBx);
        QA2 = pack_bf16(qA.y - bAy, qA.x - bAx);
        QA3 = pack_bf16(qB.y - bBy, qB.x - bBx);
    }

    float o[8][4];
#pragma unroll
    for (int n = 0; n < 8; n++)
#pragma unroll
        for (int r = 0; r < 4; r++) o[n][r] = 0.0f;
    float la0 = 0.0f, la1 = 0.0f, lb0 = 0.0f, lb1 = 0.0f;

    const u32* kpbase = g_kp + (size_t)bid * NTOK * 8;
    const __nv_bfloat16* vbbase = g_vb + (size_t)bid * CDIM * NTOK;

    const int t0 = grp * (NT / 2);
    const int t1 = t0 + (NT / 2);

    // cp.async loaders: K = 64 uint4 (lt<64, 1 each); V = 256 uint4 (2 each)
    const int vi0 = lt,        vch0 = vi0 >> 2, vk0 = vi0 & 3;
    const int vi1 = lt + 128,  vch1 = vi1 >> 2, vk1 = vi1 & 3;

#define ISSUE_TILE(tt, bu) do { \
        const int _k0 = (tt) * KT; \
        if (lt < 64) \
            cp16(smem_addr(&Kc[grp][bu][lt * 4]), kpbase + (size_t)_k0 * 8 + lt * 4); \
        cp16(smem_addr(&Vs[grp][bu][vch0 * 16 + vk0 * 4]), \
             (const char*)(vbbase + (size_t)vch0 * NTOK + _k0) + vk0 * 16); \
        cp16(smem_addr(&Vs[grp][bu][vch1 * 16 + vk1 * 4]), \
             (const char*)(vbbase + (size_t)vch1 * NTOK + _k0) + vk1 * 16); \
        CP_COMMIT(); \
    } while (0)

    // prologue: tiles t0 -> buf0, t0+1 -> buf1
    ISSUE_TILE(t0, 0);
    ISSUE_TILE(t0 + 1, 1);

    int buf = 0;
    for (int t = t0; t < t1; t++) {
        CP_WAIT1();                 // tile t landed (<=1 younger group pending)
        GBAR(barid);                // data visible group-wide; all threads done
                                    // reading buf (t-1)%3 -> safe to refill it
        if (t + 2 < t1) {
            const int wb = (buf + 2 >= 3) ? buf - 1 : buf + 2;   // (t+2)%3
            ISSUE_TILE(t + 2, wb);
        }

        const u32* kc = Kc[grp][buf];
        const u32* vs = Vs[grp][buf];

        // ---- QK: 4 n-tiles x 2 bf16-split mmas (exact to ~2^-17) ----
        float d[4][4];
#pragma unroll
        for (int nt = 0; nt < 4; nt++) {
            const uint2 kk = *(const uint2*)&kc[(nt * 8 + g) * 8 + t4 * 2];
            mma_bf16_z(d[nt], QA0, QA1, QA2, QA3, kk.x, kk.y);  // Qb.kb + Qd.kd
            mma_bf16 (d[nt], QA0, QA1, QA2, QA3, kk.y, kk.x);   // Qb.kd + Qd.kb
        }

        // ---- f32 exp2 + l + pack into PV A-frags (bf16x2) ----
        u32 pf[2][4];
#pragma unroll
        for (int s = 0; s < 2; s++) {
            const float eA0 = ex2f(d[2 * s][0]),     eA1 = ex2f(d[2 * s][1]);
            const float eB0 = ex2f(d[2 * s][2]),     eB1 = ex2f(d[2 * s][3]);
            const float fA0 = ex2f(d[2 * s + 1][0]), fA1 = ex2f(d[2 * s + 1][1]);
            const float fB0 = ex2f(d[2 * s + 1][2]), fB1 = ex2f(d[2 * s + 1][3]);
            la0 += eA0 + eA1;  la1 += fA0 + fA1;
            lb0 += eB0 + eB1;  lb1 += fB0 + fB1;
            pf[s][0] = pack_bf16(eA1, eA0);
            pf[s][1] = pack_bf16(eB1, eB0);
            pf[s][2] = pack_bf16(fA1, fA0);
            pf[s][3] = pack_bf16(fB1, fB0);
        }

        // ---- P x V: 8 n-tiles x 2 k-steps, B-frags one LDS.128 per n ----
#pragma unroll
        for (int n = 0; n < 8; n++) {
            const uint4 vv = *(const uint4*)&vs[(n * 8 + g) * 16 + t4 * 4];
            mma_bf16(o[n], pf[0][0], pf[0][1], pf[0][2], pf[0][3], vv.x, vv.y);
            mma_bf16(o[n], pf[1][0], pf[1][1], pf[1][2], pf[1][3], vv.z, vv.w);
        }

        buf = (buf + 1 >= 3) ? 0 : buf + 1;
    }

    float la = la0 + la1;
    float lb = lb0 + lb1;
    la += __shfl_xor_sync(0xffffffffu, la, 1);
    la += __shfl_xor_sync(0xffffffffu, la, 2);
    lb += __shfl_xor_sync(0xffffffffu, lb, 1);
    lb += __shfl_xor_sync(0xffffffffu, lb, 2);

    // ---- merge split-K partials ----
#pragma unroll
    for (int h = 0; h < 2; h++) {
        if (grp == 1) {
            if (h == 0 && t4 == 0) {
                lsm[rA_l] = la;
                lsm[rB_l] = lb;
            }
#pragma unroll
            for (int n = h * 4; n < h * 4 + 4; n++) {
                const int col = (n * 8 + 2 * t4) & 31;
                *(float2*)&osm[rA_l][col] = make_float2(o[n][0], o[n][1]);
                *(float2*)&osm[rB_l][col] = make_float2(o[n][2], o[n][3]);
            }
        }
        __syncthreads();
        if (grp == 0) {
            if (h == 0) { la += lsm[rA_l]; lb += lsm[rB_l]; }
#pragma unroll
            for (int n = h * 4; n < h * 4 + 4; n++) {
                const int col = (n * 8 + 2 * t4) & 31;
                const float2 ea = *(const float2*)&osm[rA_l][col];
                const float2 eb = *(const float2*)&osm[rB_l][col];
                o[n][0] += ea.x; o[n][1] += ea.y;
                o[n][2] += eb.x; o[n][3] += eb.y;
            }
        }
        __syncthreads();
    }

    if (grp == 0) {
        const float gamma = *gamma_p;
        const float gia = gamma / la;
        const float gib = gamma / lb;
        const size_t baseA = ((size_t)bid * NTOK + rowA) * CDIM;
        const size_t baseB = ((size_t)bid * NTOK + rowB) * CDIM;
#pragma unroll
        for (int n = 0; n < 8; n++) {
            const int col = n * 8 + 2 * t4;
            const float2 xvA = *(const float2*)&x[baseA + col];
            const float2 xvB = *(const float2*)&x[baseB + col];
            float2 ovA, ovB;
            ovA.x = gia * o[n][0] + xvA.x;
            ovA.y = gia * o[n][1] + xvA.y;
            ovB.x = gib * o[n][2] + xvB.x;
            ovB.y = gib * o[n][3] + xvB.y;
            *(float2*)&out[baseA + col] = ovA;
            *(float2*)&out[baseB + col] = ovB;
        }
    }
}

extern "C" void kernel_launch(void* const* d_in, const int* in_sizes, int n_in,
                              void* d_out, int out_size)
{
    const float* x     = (const float*)d_in[0];
    const float* Wf    = (const float*)d_in[1];
    const float* bf    = (const float*)d_in[2];
    const float* Wg    = (const float*)d_in[3];
    const float* bg    = (const float*)d_in[4];
    const float* Wh    = (const float*)d_in[5];
    const float* bh    = (const float*)d_in[6];
    const float* gamma = (const float*)d_in[7];
    float* out = (float*)d_out;

    proj_kernel<<<(BATCH * NTOK) / 64, 128>>>(x, Wf, bf, Wg, bg, Wh, bh);
    attn_kernel<<<dim3(NTOK / QB, BATCH), 256>>>(x, gamma, out);
}